// round 8
// baseline (speedup 1.0000x reference)
#include <cuda_runtime.h>
#include <cstdint>

// 256 independent sims of 128x128. Ping-pong u/v scratch in (b,d,y,x) layout.
static __device__ float g_u[2][(size_t)256 * 16384];
static __device__ float g_v[2][(size_t)256 * 16384];

// ---- constants (double, cast to float to mirror numpy f32 ops) ----
constexpr double DXd  = 2.0 / 9.0;      // 2/(B+1), B=8
constexpr double DYd  = 2.0 / 127.0;    // 2/(H+1), H=126
constexpr double DX2d = DXd * DXd;
constexpr double DY2d = DYd * DYd;
constexpr double DENd = 2.0 * (DX2d + DY2d);

constexpr float DX2F   = (float)DX2d;
constexpr float DY2F   = (float)DY2d;
constexpr float INVDEN = (float)(1.0 / DENd);
constexpr float CF     = (float)(DX2d * DY2d / DENd);
constexpr float INV2DX = (float)(1.0 / (2.0 * DXd));
constexpr float INV2DY = (float)(1.0 / (2.0 * DYd));
constexpr float INVDT  = 10.0f;
constexpr float DTDX   = (float)(0.1 / DXd);
constexpr float DTDY   = (float)(0.1 / DYd);
constexpr float DTDX2  = (float)(0.1 / DX2d);
constexpr float DTDY2  = (float)(0.1 / DY2d);
constexpr float NUF    = 0.1f;
constexpr float PXC    = (float)(0.1 / (2.0 * DXd));   // DT/(2*RHO*DX)
constexpr float PYC    = (float)(0.1 / (2.0 * DYd));   // DT/(2*RHO*DY)
constexpr float FDT    = 0.1f;                         // FRC*DT

// ---------------------------------------------------------------------------
// K1: transpose u0,v0 from (b, yx, d) -> (b, d, yx) into g_u[0]/g_v[0]
// grid (512, 8), block (32, 8)
// ---------------------------------------------------------------------------
__global__ void transpose_uv(const float* __restrict__ u0,
                             const float* __restrict__ v0) {
    __shared__ float tu[32][33];
    __shared__ float tv[32][33];
    const int b   = blockIdx.y;
    const int yx0 = blockIdx.x * 32;
    const int tx  = threadIdx.x;
    const int ty  = threadIdx.y;

    const float* ub = u0 + (size_t)b * 16384 * 32;
    const float* vb = v0 + (size_t)b * 16384 * 32;
    #pragma unroll
    for (int r = ty; r < 32; r += 8) {
        tu[r][tx] = ub[(size_t)(yx0 + r) * 32 + tx];
        tv[r][tx] = vb[(size_t)(yx0 + r) * 32 + tx];
    }
    __syncthreads();
    #pragma unroll
    for (int r = ty; r < 32; r += 8) {   // r = d, tx = local yx
        size_t o = ((size_t)b * 32 + r) * 16384 + yx0 + tx;
        g_u[0][o] = tu[tx][r];
        g_v[0][o] = tv[tx][r];
    }
}

// ---------------------------------------------------------------------------
// K2: persistent sim kernel. One CTA per (b,d). p resides in smem (64 KB).
// 512 threads: ty = t>>7 in [0,4), tx = t&127. Rows y = 1+ty+4k, k<32.
// ---------------------------------------------------------------------------
__global__ void __launch_bounds__(512) sim_kernel(
    const float* __restrict__ xin,    // (8,126,126,64)
    const float* __restrict__ w,      // (32,64)
    const float* __restrict__ b_lin,  // (32,)
    float* __restrict__ out)          // (8,128,32)
{
    extern __shared__ float sp[];     // 128*128 pressure grid
    const int t  = threadIdx.x;
    const int bi = blockIdx.x;        // bi = b*32 + d
    const int b  = bi >> 5;
    const int d  = bi & 31;

    const float bl = __ldg(&b_lin[d]);

    // ---- p init: p = pad(x) . w[d] + b_lin[d]; borders = b_lin[d] ----
    float wr[64];
    #pragma unroll
    for (int f = 0; f < 64; ++f) wr[f] = __ldg(&w[d * 64 + f]);

    for (int i = t; i < 16384; i += 512) sp[i] = bl;   // borders (prefill all)
    __syncthreads();

    const float4* xb = (const float4*)(xin + (size_t)b * 126 * 126 * 64);
    for (int pi = t; pi < 126 * 126; pi += 512) {
        const int y  = pi / 126;        // 0..125 -> grid row y+1
        const int xx = pi - y * 126;    // 0..125 -> grid col xx+1
        const float4* xv = xb + (size_t)pi * 16;
        float a0 = 0.f, a1 = 0.f, a2 = 0.f, a3 = 0.f;
        #pragma unroll
        for (int j = 0; j < 16; ++j) {
            float4 q = __ldg(xv + j);
            a0 = fmaf(q.x, wr[4 * j + 0], a0);
            a1 = fmaf(q.y, wr[4 * j + 1], a1);
            a2 = fmaf(q.z, wr[4 * j + 2], a2);
            a3 = fmaf(q.w, wr[4 * j + 3], a3);
        }
        sp[(y + 1) * 128 + (xx + 1)] = (a0 + a1) + (a2 + a3) + bl;
    }
    __syncthreads();

    const int ty  = t >> 7;
    const int tx  = t & 127;
    const int xop = (tx == 127) ? (1 - 128) : 1;   // periodic x+1
    const int xom = (tx == 0) ? 127 : -1;          // periodic x-1
    const size_t so = (size_t)bi * 16384;

    float cb[32];   // c*b for this thread's rows — private, never shared

    for (int it = 0; it < 3; ++it) {
        const float* __restrict__ up = g_u[it & 1] + so;
        const float* __restrict__ vp = g_v[it & 1] + so;
        float* __restrict__ uo = g_u[(it & 1) ^ 1] + so;
        float* __restrict__ vo = g_v[(it & 1) ^ 1] + so;

        // ---- build c*b (registers only) ----
        #pragma unroll
        for (int k = 0; k < 32; ++k) {
            const int y = 1 + ty + 4 * k;
            if (y <= 126) {
                const int i = y * 128 + tx;
                float dudx = (up[i + xop] - up[i + xom]) * INV2DX;
                float dvdy = (vp[i + 128] - vp[i - 128]) * INV2DY;
                float dudy = (up[i + 128] - up[i - 128]) * INV2DY;
                float dvdx = (vp[i + xop] - vp[i + xom]) * INV2DX;
                cb[k] = CF * ((dudx + dvdy) * INVDT - dudx * dudx
                              - 2.0f * dudy * dvdx - dvdy * dvdy);
            }
        }
        __syncthreads();

        // ---- 20 Jacobi sweeps on smem p ----
        for (int s = 0; s < 20; ++s) {
            float nv[32];
            #pragma unroll
            for (int k = 0; k < 32; ++k) {
                const int y = 1 + ty + 4 * k;
                if (y <= 126) {
                    const int i = y * 128 + tx;
                    float e  = sp[i + xop], wv = sp[i + xom];
                    float n  = sp[i + 128], sv = sp[i - 128];
                    nv[k] = ((e + wv) * DY2F + (n + sv) * DX2F) * INVDEN - cb[k];
                }
            }
            __syncthreads();
            #pragma unroll
            for (int k = 0; k < 32; ++k) {
                const int y = 1 + ty + 4 * k;
                if (y <= 126) {
                    sp[y * 128 + tx] = nv[k];
                    if (ty == 0 && k == 0)  sp[tx] = nv[k];               // p[0]=p[1]
                    if (ty == 1 && k == 31) sp[127 * 128 + tx] = nv[k];   // p[127]=p[126]
                }
            }
            __syncthreads();
        }

        // ---- velocity step: read up/vp (old) + sp, write uo/vo (ping-pong) ----
        #pragma unroll 2
        for (int k = 0; k < 32; ++k) {
            const int y = 1 + ty + 4 * k;
            if (y <= 126) {
                const int i = y * 128 + tx;
                float uc = up[i], uW = up[i + xom], uE = up[i + xop];
                float uS = up[i - 128], uN = up[i + 128];
                float vc = vp[i], vW = vp[i + xom], vE = vp[i + xop];
                float vS = vp[i - 128], vN = vp[i + 128];
                float pE = sp[i + xop], pW = sp[i + xom];
                float pN = sp[i + 128], pS = sp[i - 128];
                float lapu = DTDX2 * (uE - 2.f * uc + uW) + DTDY2 * (uN - 2.f * uc + uS);
                float lapv = DTDX2 * (vE - 2.f * vc + vW) + DTDY2 * (vN - 2.f * vc + vS);
                uo[i] = uc - uc * DTDX * (uc - uW) - vc * DTDY * (uc - uS)
                        - PXC * (pE - pW) + NUF * lapu + FDT;
                vo[i] = vc - uc * DTDX * (vc - vW) - vc * DTDY * (vc - vS)
                        - PYC * (pN - pS) + NUF * lapv;
            }
        }
        // rows 0 and 127 of u,v set to 0
        if (t < 128)      { uo[t] = 0.f; vo[t] = 0.f; }
        else if (t < 256) { uo[127 * 128 + (t - 128)] = 0.f;
                            vo[127 * 128 + (t - 128)] = 0.f; }
        __syncthreads();  // global+shared visibility within the block
    }

    // output: p[:, -1, :, :]  (row 127, maintained == row 126)
    if (t < 128) out[((size_t)b * 128 + t) * 32 + d] = sp[127 * 128 + t];
}

// ---------------------------------------------------------------------------
extern "C" void kernel_launch(void* const* d_in, const int* in_sizes, int n_in,
                              void* d_out, int out_size) {
    const float* x  = (const float*)d_in[0];   // (8,126,126,64)
    const float* u0 = (const float*)d_in[1];   // (8,128,128,32)
    const float* v0 = (const float*)d_in[2];   // (8,128,128,32)
    const float* w  = (const float*)d_in[3];   // (32,64)
    const float* bl = (const float*)d_in[4];   // (32,)
    float* out = (float*)d_out;                // (8,128,32)

    (void)in_sizes; (void)n_in; (void)out_size;

    static bool attr_set = false;
    if (!attr_set) {
        cudaFuncSetAttribute(sim_kernel,
                             cudaFuncAttributeMaxDynamicSharedMemorySize, 65536);
        attr_set = true;
    }

    transpose_uv<<<dim3(512, 8), dim3(32, 8)>>>(u0, v0);
    sim_kernel<<<256, 512, 65536>>>(x, w, bl, out);
}

// round 10
// speedup vs baseline: 2.8200x; 2.8200x over previous
#include <cuda_runtime.h>
#include <cstdint>

// 256 independent sims of 128x128. Ping-pong u/v scratch + precomputed p-init,
// all in (b,d,y,x) layout.
static __device__ float g_u[2][(size_t)256 * 16384];
static __device__ float g_v[2][(size_t)256 * 16384];
static __device__ float g_p[(size_t)256 * 16384];

// ---- constants (double, cast to float to mirror numpy f32 ops) ----
constexpr double DXd  = 2.0 / 9.0;      // 2/(B+1), B=8
constexpr double DYd  = 2.0 / 127.0;    // 2/(H+1), H=126
constexpr double DX2d = DXd * DXd;
constexpr double DY2d = DYd * DYd;
constexpr double DENd = 2.0 * (DX2d + DY2d);

constexpr float AEW    = (float)(DY2d / DENd);   // coeff for (E+W)
constexpr float ANS    = (float)(DX2d / DENd);   // coeff for (N+S)
constexpr float CF     = (float)(DX2d * DY2d / DENd);
constexpr float INV2DX = (float)(1.0 / (2.0 * DXd));
constexpr float INV2DY = (float)(1.0 / (2.0 * DYd));
constexpr float INVDT  = 10.0f;
constexpr float DTDX   = (float)(0.1 / DXd);
constexpr float DTDY   = (float)(0.1 / DYd);
constexpr float DTDX2  = (float)(0.1 / DX2d);
constexpr float DTDY2  = (float)(0.1 / DY2d);
constexpr float NUF    = 0.1f;
constexpr float PXC    = (float)(0.1 / (2.0 * DXd));   // DT/(2*RHO*DX)
constexpr float PYC    = (float)(0.1 / (2.0 * DYd));   // DT/(2*RHO*DY)
constexpr float FDT    = 0.1f;                         // FRC*DT

// ---------------------------------------------------------------------------
// K1: transpose u0,v0 from (b, yx, d) -> (b, d, yx) into g_u[0]/g_v[0]
// ---------------------------------------------------------------------------
__global__ void transpose_uv(const float* __restrict__ u0,
                             const float* __restrict__ v0) {
    __shared__ float tu[32][33];
    __shared__ float tv[32][33];
    const int b   = blockIdx.y;
    const int yx0 = blockIdx.x * 32;
    const int tx  = threadIdx.x;
    const int ty  = threadIdx.y;

    const float* ub = u0 + (size_t)b * 16384 * 32;
    const float* vb = v0 + (size_t)b * 16384 * 32;
    #pragma unroll
    for (int r = ty; r < 32; r += 8) {
        tu[r][tx] = ub[(size_t)(yx0 + r) * 32 + tx];
        tv[r][tx] = vb[(size_t)(yx0 + r) * 32 + tx];
    }
    __syncthreads();
    #pragma unroll
    for (int r = ty; r < 32; r += 8) {   // r = d, tx = local yx
        size_t o = ((size_t)b * 32 + r) * 16384 + yx0 + tx;
        g_u[0][o] = tu[tx][r];
        g_v[0][o] = tv[tx][r];
    }
}

// ---------------------------------------------------------------------------
// K2: p-init einsum: g_p[b,d,y,x] = dot(x[b,y-1,x-1,:], w[d]) + b_lin[d],
// borders (y in {0,127} or x in {0,127}) = b_lin[d].
// grid (128, 8), block 128 (tx = x).
// ---------------------------------------------------------------------------
__global__ void __launch_bounds__(128) einsum_p(
    const float* __restrict__ x, const float* __restrict__ w,
    const float* __restrict__ b_lin)
{
    __shared__ float ws[2048];
    __shared__ float bls[32];
    const int y  = blockIdx.x;
    const int b  = blockIdx.y;
    const int tx = threadIdx.x;
    for (int i = tx; i < 2048; i += 128) ws[i] = __ldg(w + i);
    if (tx < 32) bls[tx] = __ldg(b_lin + tx);
    __syncthreads();

    float* gp = g_p + ((size_t)b << 19) + y * 128 + tx;   // stride 16384 per d
    if (y == 0 || y == 127 || tx == 0 || tx == 127) {
        #pragma unroll 1
        for (int d = 0; d < 32; ++d) gp[(size_t)d << 14] = bls[d];
        return;
    }
    float xv[64];
    const float4* xr = (const float4*)(x +
        (((size_t)b * 126 + (y - 1)) * 126 + (tx - 1)) * 64);
    #pragma unroll
    for (int i = 0; i < 16; ++i) {
        float4 q = __ldg(xr + i);
        xv[4*i] = q.x; xv[4*i+1] = q.y; xv[4*i+2] = q.z; xv[4*i+3] = q.w;
    }
    #pragma unroll 1
    for (int d = 0; d < 32; ++d) {
        const float4* wv = (const float4*)(ws + (d << 6));
        float a0 = 0.f, a1 = 0.f, a2 = 0.f, a3 = 0.f;
        #pragma unroll
        for (int i = 0; i < 16; ++i) {
            float4 q = wv[i];
            a0 = fmaf(xv[4*i],   q.x, a0);
            a1 = fmaf(xv[4*i+1], q.y, a1);
            a2 = fmaf(xv[4*i+2], q.z, a2);
            a3 = fmaf(xv[4*i+3], q.w, a3);
        }
        gp[(size_t)d << 14] = (a0 + a1) + (a2 + a3) + bls[d];
    }
}

// Jacobi row update: out = (W+E)*AEW + (S+N)*ANS + mcb, periodic x via shfl.
__device__ __forceinline__ void jrow(const float cur[4], const float S[4],
                                     const float N[4], const float m[4],
                                     int lm, int lp, float out[4]) {
    float wL = __shfl_sync(0xffffffffu, cur[3], lm);
    float eR = __shfl_sync(0xffffffffu, cur[0], lp);
    out[0] = fmaf(wL     + cur[1], AEW, fmaf(S[0] + N[0], ANS, m[0]));
    out[1] = fmaf(cur[0] + cur[2], AEW, fmaf(S[1] + N[1], ANS, m[1]));
    out[2] = fmaf(cur[1] + cur[3], AEW, fmaf(S[2] + N[2], ANS, m[2]));
    out[3] = fmaf(cur[2] + eR,     AEW, fmaf(S[3] + N[3], ANS, m[3]));
}

// ---------------------------------------------------------------------------
// K3: persistent sim kernel. One CTA per (b,d). p register-resident:
// warp w owns rows 8w..8w+7; lane l owns x = 4l..4l+3. Halo rows via smem.
// ---------------------------------------------------------------------------
__global__ void __launch_bounds__(512, 1) sim_kernel(float* __restrict__ out)
{
    __shared__ float halo[2 * 2 * 16 * 128];   // [parity][top/bot][warp][x], 32 KB
    const int t   = threadIdx.x;
    const int wid = t >> 5;
    const int l   = t & 31;
    const int bi  = blockIdx.x;
    const int b   = bi >> 5, d = bi & 31;
    const int y0  = wid << 3;
    const int x0  = l << 2;
    const size_t so = (size_t)bi << 14;

    const int xm = (x0 + 127) & 127;   // x0-1, periodic
    const int xp = (x0 + 4)   & 127;   // x0+4, periodic
    const int lm = (l + 31) & 31;
    const int lp = (l + 1)  & 31;

    // ---- load p-init (registers) ----
    float p[8][4];
    {
        const float4* gp = (const float4*)(g_p + so);
        #pragma unroll
        for (int r = 0; r < 8; ++r) {
            float4 q = __ldg(gp + ((y0 + r) << 5) + l);
            p[r][0] = q.x; p[r][1] = q.y; p[r][2] = q.z; p[r][3] = q.w;
        }
    }

    float mcb[8][4];
    #pragma unroll
    for (int r = 0; r < 8; ++r)
        #pragma unroll
        for (int j = 0; j < 4; ++j) mcb[r][j] = 0.f;

    #pragma unroll 1
    for (int it = 0; it < 3; ++it) {
        const float* __restrict__ up = g_u[it & 1] + so;
        const float* __restrict__ vp = g_v[it & 1] + so;
        float* __restrict__ uo = g_u[(it & 1) ^ 1] + so;
        float* __restrict__ vo = g_v[(it & 1) ^ 1] + so;

        // ---- build_b -> mcb = -c*b (registers only) ----
        #pragma unroll
        for (int r = 0; r < 8; ++r) {
            const int y = y0 + r;
            if (y >= 1 && y <= 126) {
                const float* uy = up + (y << 7);
                const float* vy = vp + (y << 7);
                float4 uc4 = __ldg((const float4*)(uy + x0));
                float  uL  = __ldg(uy + xm), uR = __ldg(uy + xp);
                float4 uN4 = __ldg((const float4*)(uy + 128 + x0));
                float4 uS4 = __ldg((const float4*)(uy - 128 + x0));
                float4 vc4 = __ldg((const float4*)(vy + x0));
                float  vL  = __ldg(vy + xm), vR = __ldg(vy + xp);
                float4 vN4 = __ldg((const float4*)(vy + 128 + x0));
                float4 vS4 = __ldg((const float4*)(vy - 128 + x0));
                float ue[4] = {uc4.y, uc4.z, uc4.w, uR};
                float uw[4] = {uL, uc4.x, uc4.y, uc4.z};
                float ve[4] = {vc4.y, vc4.z, vc4.w, vR};
                float vw[4] = {vL, vc4.x, vc4.y, vc4.z};
                float un_[4] = {uN4.x, uN4.y, uN4.z, uN4.w};
                float us_[4] = {uS4.x, uS4.y, uS4.z, uS4.w};
                float vn_[4] = {vN4.x, vN4.y, vN4.z, vN4.w};
                float vs_[4] = {vS4.x, vS4.y, vS4.z, vS4.w};
                #pragma unroll
                for (int j = 0; j < 4; ++j) {
                    float dudx = (ue[j] - uw[j]) * INV2DX;
                    float dvdy = (vn_[j] - vs_[j]) * INV2DY;
                    float dudy = (un_[j] - us_[j]) * INV2DY;
                    float dvdx = (ve[j] - vw[j]) * INV2DX;
                    float bt = (dudx + dvdy) * INVDT - dudx * dudx
                               - 2.0f * dudy * dvdx - dvdy * dvdy;
                    mcb[r][j] = -CF * bt;
                }
            }
        }

        // ---- 20 Jacobi sweeps, p in registers, halo rows via smem ----
        #pragma unroll 1
        for (int s = 0; s < 20; ++s) {
            float* hb = halo + (s & 1) * 4096;
            *(float4*)(hb + (wid << 7) + x0) =
                make_float4(p[0][0], p[0][1], p[0][2], p[0][3]);
            *(float4*)(hb + ((16 + wid) << 7) + x0) =
                make_float4(p[7][0], p[7][1], p[7][2], p[7][3]);
            __syncthreads();
            float hA[4] = {0,0,0,0}, hB[4] = {0,0,0,0};
            if (wid > 0) {
                float4 q = *(const float4*)(hb + ((15 + wid) << 7) + x0);
                hA[0]=q.x; hA[1]=q.y; hA[2]=q.z; hA[3]=q.w;
            }
            if (wid < 15) {
                float4 q = *(const float4*)(hb + ((wid + 1) << 7) + x0);
                hB[0]=q.x; hB[1]=q.y; hB[2]=q.z; hB[3]=q.w;
            }

            float tS[4], nv[4];
            if (wid == 0) {   // y=0: mirror row, no compute
                tS[0]=p[0][0]; tS[1]=p[0][1]; tS[2]=p[0][2]; tS[3]=p[0][3];
            } else {
                jrow(p[0], hA, p[1], mcb[0], lm, lp, nv);
                tS[0]=p[0][0]; tS[1]=p[0][1]; tS[2]=p[0][2]; tS[3]=p[0][3];
                p[0][0]=nv[0]; p[0][1]=nv[1]; p[0][2]=nv[2]; p[0][3]=nv[3];
            }
            #pragma unroll
            for (int r = 1; r < 7; ++r) {
                jrow(p[r], tS, p[r + 1], mcb[r], lm, lp, nv);
                float o0=p[r][0], o1=p[r][1], o2=p[r][2], o3=p[r][3];
                p[r][0]=nv[0]; p[r][1]=nv[1]; p[r][2]=nv[2]; p[r][3]=nv[3];
                tS[0]=o0; tS[1]=o1; tS[2]=o2; tS[3]=o3;
            }
            if (wid < 15) {   // y=8w+7 (y=127 is mirror, skipped)
                jrow(p[7], tS, hB, mcb[7], lm, lp, nv);
                p[7][0]=nv[0]; p[7][1]=nv[1]; p[7][2]=nv[2]; p[7][3]=nv[3];
            }
            if (wid == 0) {   // p[0] = p[1] (new)
                p[0][0]=p[1][0]; p[0][1]=p[1][1]; p[0][2]=p[1][2]; p[0][3]=p[1][3];
            }
            if (wid == 15) {  // p[127] = p[126] (new)
                p[7][0]=p[6][0]; p[7][1]=p[6][1]; p[7][2]=p[6][2]; p[7][3]=p[6][3];
            }
        }

        // ---- exchange final p halos for velocity (parity buf 0) ----
        *(float4*)(halo + (wid << 7) + x0) =
            make_float4(p[0][0], p[0][1], p[0][2], p[0][3]);
        *(float4*)(halo + ((16 + wid) << 7) + x0) =
            make_float4(p[7][0], p[7][1], p[7][2], p[7][3]);
        __syncthreads();
        float pA[4] = {0,0,0,0}, pB[4] = {0,0,0,0};
        if (wid > 0) {
            float4 q = *(const float4*)(halo + ((15 + wid) << 7) + x0);
            pA[0]=q.x; pA[1]=q.y; pA[2]=q.z; pA[3]=q.w;
        }
        if (wid < 15) {
            float4 q = *(const float4*)(halo + ((wid + 1) << 7) + x0);
            pB[0]=q.x; pB[1]=q.y; pB[2]=q.z; pB[3]=q.w;
        }

        // ---- velocity step: read up/vp + p(regs), write uo/vo ----
        #pragma unroll
        for (int r = 0; r < 8; ++r) {
            const int y = y0 + r;
            float* uoy = uo + (y << 7);
            float* voy = vo + (y << 7);
            if (y == 0 || y == 127) {
                *(float4*)(uoy + x0) = make_float4(0.f, 0.f, 0.f, 0.f);
                *(float4*)(voy + x0) = make_float4(0.f, 0.f, 0.f, 0.f);
            } else {
                const float* uy = up + (y << 7);
                const float* vy = vp + (y << 7);
                float4 uc4 = __ldg((const float4*)(uy + x0));
                float  uL  = __ldg(uy + xm), uR = __ldg(uy + xp);
                float4 uN4 = __ldg((const float4*)(uy + 128 + x0));
                float4 uS4 = __ldg((const float4*)(uy - 128 + x0));
                float4 vc4 = __ldg((const float4*)(vy + x0));
                float  vL  = __ldg(vy + xm), vR = __ldg(vy + xp);
                float4 vN4 = __ldg((const float4*)(vy + 128 + x0));
                float4 vS4 = __ldg((const float4*)(vy - 128 + x0));

                float ucv[4] = {uc4.x, uc4.y, uc4.z, uc4.w};
                float ue[4]  = {uc4.y, uc4.z, uc4.w, uR};
                float uw[4]  = {uL, uc4.x, uc4.y, uc4.z};
                float un_[4] = {uN4.x, uN4.y, uN4.z, uN4.w};
                float us_[4] = {uS4.x, uS4.y, uS4.z, uS4.w};
                float vcv[4] = {vc4.x, vc4.y, vc4.z, vc4.w};
                float ve[4]  = {vc4.y, vc4.z, vc4.w, vR};
                float vw[4]  = {vL, vc4.x, vc4.y, vc4.z};
                float vn_[4] = {vN4.x, vN4.y, vN4.z, vN4.w};
                float vs_[4] = {vS4.x, vS4.y, vS4.z, vS4.w};

                float wLp = __shfl_sync(0xffffffffu, p[r][3], lm);
                float eRp = __shfl_sync(0xffffffffu, p[r][0], lp);
                float pe[4] = {p[r][1], p[r][2], p[r][3], eRp};
                float pw[4] = {wLp, p[r][0], p[r][1], p[r][2]};
                float ps_[4], pn_[4];
                #pragma unroll
                for (int j = 0; j < 4; ++j) {
                    ps_[j] = (r == 0) ? pA[j] : p[r - 1 < 0 ? 0 : r - 1][j];
                    pn_[j] = (r == 7) ? pB[j] : p[r + 1 > 7 ? 7 : r + 1][j];
                }

                float unew[4], vnew[4];
                #pragma unroll
                for (int j = 0; j < 4; ++j) {
                    float uc = ucv[j], vc = vcv[j];
                    float lapu = DTDX2 * (ue[j] - 2.f * uc + uw[j])
                               + DTDY2 * (un_[j] - 2.f * uc + us_[j]);
                    float lapv = DTDX2 * (ve[j] - 2.f * vc + vw[j])
                               + DTDY2 * (vn_[j] - 2.f * vc + vs_[j]);
                    unew[j] = uc - uc * DTDX * (uc - uw[j]) - vc * DTDY * (uc - us_[j])
                              - PXC * (pe[j] - pw[j]) + NUF * lapu + FDT;
                    vnew[j] = vc - uc * DTDX * (vc - vw[j]) - vc * DTDY * (vc - vs_[j])
                              - PYC * (pn_[j] - ps_[j]) + NUF * lapv;
                }
                *(float4*)(uoy + x0) = make_float4(unew[0], unew[1], unew[2], unew[3]);
                *(float4*)(voy + x0) = make_float4(vnew[0], vnew[1], vnew[2], vnew[3]);
            }
        }
        __syncthreads();   // global u/v visibility + halo buffer reuse safety
    }

    // ---- output: p[:, -1, :, :] = row 127 (mirror of 126, in warp 15 regs) ----
    if (wid == 15) {
        #pragma unroll
        for (int j = 0; j < 4; ++j)
            out[(size_t)b * 4096 + (size_t)(x0 + j) * 32 + d] = p[7][j];
    }
}

// ---------------------------------------------------------------------------
extern "C" void kernel_launch(void* const* d_in, const int* in_sizes, int n_in,
                              void* d_out, int out_size) {
    const float* x  = (const float*)d_in[0];   // (8,126,126,64)
    const float* u0 = (const float*)d_in[1];   // (8,128,128,32)
    const float* v0 = (const float*)d_in[2];   // (8,128,128,32)
    const float* w  = (const float*)d_in[3];   // (32,64)
    const float* bl = (const float*)d_in[4];   // (32,)
    float* out = (float*)d_out;                // (8,128,32)

    (void)in_sizes; (void)n_in; (void)out_size;

    transpose_uv<<<dim3(512, 8), dim3(32, 8)>>>(u0, v0);
    einsum_p<<<dim3(128, 8), 128>>>(x, w, bl);
    sim_kernel<<<256, 512>>>(out);
}

// round 11
// speedup vs baseline: 3.1212x; 1.1068x over previous
#include <cuda_runtime.h>
#include <cstdint>

// 256 independent sims of 128x128. Ping-pong u/v scratch + precomputed p-init,
// all in (b,d,y,x) layout.
static __device__ float g_u[2][(size_t)256 * 16384];
static __device__ float g_v[2][(size_t)256 * 16384];
static __device__ float g_p[(size_t)256 * 16384];

// ---- constants (double, cast to float to mirror numpy f32 ops) ----
constexpr double DXd  = 2.0 / 9.0;      // 2/(B+1), B=8
constexpr double DYd  = 2.0 / 127.0;    // 2/(H+1), H=126
constexpr double DX2d = DXd * DXd;
constexpr double DY2d = DYd * DYd;
constexpr double DENd = 2.0 * (DX2d + DY2d);

constexpr float AEW    = (float)(DY2d / DENd);   // coeff for (E+W)
constexpr float ANS    = (float)(DX2d / DENd);   // coeff for (N+S)
constexpr float CF     = (float)(DX2d * DY2d / DENd);
constexpr float INV2DX = (float)(1.0 / (2.0 * DXd));
constexpr float INV2DY = (float)(1.0 / (2.0 * DYd));
constexpr float INVDT  = 10.0f;
constexpr float DTDX   = (float)(0.1 / DXd);
constexpr float DTDY   = (float)(0.1 / DYd);
constexpr float DTDX2  = (float)(0.1 / DX2d);
constexpr float DTDY2  = (float)(0.1 / DY2d);
constexpr float NUF    = 0.1f;
constexpr float PXC    = (float)(0.1 / (2.0 * DXd));   // DT/(2*RHO*DX)
constexpr float PYC    = (float)(0.1 / (2.0 * DYd));   // DT/(2*RHO*DY)
constexpr float FDT    = 0.1f;                         // FRC*DT

typedef unsigned long long ull;

// ---- packed f32x2 helpers ----
__device__ __forceinline__ ull pk2(float lo, float hi) {
    ull r; asm("mov.b64 %0, {%1,%2};" : "=l"(r) : "f"(lo), "f"(hi)); return r;
}
__device__ __forceinline__ void upk2(ull v, float& lo, float& hi) {
    asm("mov.b64 {%0,%1}, %2;" : "=f"(lo), "=f"(hi) : "l"(v));
}
__device__ __forceinline__ ull add2_(ull a, ull b) {
    ull d; asm("add.rn.f32x2 %0, %1, %2;" : "=l"(d) : "l"(a), "l"(b)); return d;
}
__device__ __forceinline__ ull fma2_(ull a, ull b, ull c) {
    ull d; asm("fma.rn.f32x2 %0, %1, %2, %3;" : "=l"(d) : "l"(a), "l"(b), "l"(c)); return d;
}

// ---------------------------------------------------------------------------
// K1 (fused prep): blocks [0,4096) transpose u0,v0 (b,yx,d)->(b,d,yx);
// blocks [4096,4608) compute p-init einsum into g_p.
// 256 threads per block.
// ---------------------------------------------------------------------------
__global__ void __launch_bounds__(256) prep_kernel(
    const float* __restrict__ u0, const float* __restrict__ v0,
    const float* __restrict__ x,  const float* __restrict__ w,
    const float* __restrict__ b_lin)
{
    __shared__ float s0[32][33];
    __shared__ float s1[32][33];
    const int bid = blockIdx.x;
    const int t   = threadIdx.x;

    if (bid < 4096) {
        // ---- transpose role ----
        const int b   = bid >> 9;
        const int yx0 = (bid & 511) * 32;
        const int tx  = t & 31;
        const int ty  = t >> 5;          // 0..7
        const float* ub = u0 + (size_t)b * 16384 * 32;
        const float* vb = v0 + (size_t)b * 16384 * 32;
        #pragma unroll
        for (int r = ty; r < 32; r += 8) {
            s0[r][tx] = ub[(size_t)(yx0 + r) * 32 + tx];
            s1[r][tx] = vb[(size_t)(yx0 + r) * 32 + tx];
        }
        __syncthreads();
        #pragma unroll
        for (int r = ty; r < 32; r += 8) {   // r = d, tx = local yx
            size_t o = ((size_t)b * 32 + r) * 16384 + yx0 + tx;
            g_u[0][o] = s0[tx][r];
            g_v[0][o] = s1[tx][r];
        }
    } else {
        // ---- einsum role: 512 blocks, 2 rows each ----
        float* ws  = &s0[0][0];           // 2048 floats fit in s0+s1 (2112)
        float* bls = &s1[31][0];          // 32 floats, disjoint tail
        for (int i = t; i < 2048; i += 256) ws[i] = __ldg(w + i);
        if (t < 32) bls[t] = __ldg(b_lin + t);
        __syncthreads();

        const int bid2 = bid - 4096;                       // 0..511
        const int b    = bid2 >> 6;
        const int y    = ((bid2 & 63) << 1) | (t >> 7);    // 0..127
        const int tx   = t & 127;

        float* gp = g_p + ((size_t)b << 19) + y * 128 + tx;  // +d*16384
        if (y == 0 || y == 127 || tx == 0 || tx == 127) {
            #pragma unroll 1
            for (int d = 0; d < 32; ++d) gp[(size_t)d << 14] = bls[d];
            return;
        }
        float xv[64];
        const float4* xr = (const float4*)(x +
            (((size_t)b * 126 + (y - 1)) * 126 + (tx - 1)) * 64);
        #pragma unroll
        for (int i = 0; i < 16; ++i) {
            float4 q = __ldg(xr + i);
            xv[4*i] = q.x; xv[4*i+1] = q.y; xv[4*i+2] = q.z; xv[4*i+3] = q.w;
        }
        #pragma unroll 1
        for (int d = 0; d < 32; ++d) {
            const float4* wv = (const float4*)(ws + (d << 6));
            float a0 = 0.f, a1 = 0.f, a2 = 0.f, a3 = 0.f;
            #pragma unroll
            for (int i = 0; i < 16; ++i) {
                float4 q = wv[i];
                a0 = fmaf(xv[4*i],   q.x, a0);
                a1 = fmaf(xv[4*i+1], q.y, a1);
                a2 = fmaf(xv[4*i+2], q.z, a2);
                a3 = fmaf(xv[4*i+3], q.w, a3);
            }
            gp[(size_t)d << 14] = (a0 + a1) + (a2 + a3) + bls[d];
        }
    }
}

// Packed Jacobi row update. (a,b) = row slots {0,1},{2,3}. 2 shfl + 8 f32x2.
__device__ __forceinline__ void jrow2(ull a, ull bq, ull SA, ull SB,
                                      ull NA, ull NB, ull mA, ull mB,
                                      ull AEW2, ull ANS2, int lm, int lp,
                                      ull& oA, ull& oB)
{
    float c0, c1, c2, c3;
    upk2(a, c0, c1); upk2(bq, c2, c3);
    float wL = __shfl_sync(0xffffffffu, c3, lm);
    float eR = __shfl_sync(0xffffffffu, c0, lp);
    ull W01 = pk2(wL, c0);
    ull M   = pk2(c1, c2);     // E of {0,1} == W of {2,3}
    ull E23 = pk2(c3, eR);
    oA = fma2_(add2_(W01, M), AEW2, fma2_(add2_(SA, NA), ANS2, mA));
    oB = fma2_(add2_(M, E23), AEW2, fma2_(add2_(SB, NB), ANS2, mB));
}

// ---------------------------------------------------------------------------
// K2: persistent sim kernel. One CTA per (b,d). p register-resident (packed):
// warp w owns rows 8w..8w+7; lane l owns x = 4l..4l+3. Halo rows via smem.
// ---------------------------------------------------------------------------
__global__ void __launch_bounds__(512, 1) sim_kernel(float* __restrict__ out)
{
    __shared__ float halo[2 * 2 * 16 * 128];   // 32 KB, double-buffered
    const int t   = threadIdx.x;
    const int wid = t >> 5;
    const int l   = t & 31;
    const int bi  = blockIdx.x;
    const int b   = bi >> 5, d = bi & 31;
    const int y0  = wid << 3;
    const int x0  = l << 2;
    const size_t so = (size_t)bi << 14;

    const int lm = (l + 31) & 31;
    const int lp = (l + 1)  & 31;

    const ull AEW2 = pk2(AEW, AEW);
    const ull ANS2 = pk2(ANS, ANS);

    // ---- load p-init into packed registers ----
    ull pA[8], pB[8];
    {
        const float4* gp = (const float4*)(g_p + so);
        #pragma unroll
        for (int r = 0; r < 8; ++r) {
            float4 q = __ldg(gp + ((y0 + r) << 5) + l);
            pA[r] = pk2(q.x, q.y);
            pB[r] = pk2(q.z, q.w);
        }
    }

    ull mA[8], mB[8];

    #pragma unroll 1
    for (int it = 0; it < 3; ++it) {
        const float4* __restrict__ up4 = (const float4*)(g_u[it & 1] + so);
        const float4* __restrict__ vp4 = (const float4*)(g_v[it & 1] + so);
        float* __restrict__ uo = g_u[(it & 1) ^ 1] + so;
        float* __restrict__ vo = g_v[(it & 1) ^ 1] + so;

        // ---- build_b -> mcb (packed, registers). Rolling 3-row window. ----
        {
            float4 uP4 = make_float4(0,0,0,0), vP4 = uP4;
            float4 uN4 = uP4, vN4 = uP4;
            float4 uC4 = __ldg(up4 + (y0 << 5) + l);
            float4 vC4 = __ldg(vp4 + (y0 << 5) + l);
            if (wid > 0) {
                uP4 = __ldg(up4 + ((y0 - 1) << 5) + l);
                vP4 = __ldg(vp4 + ((y0 - 1) << 5) + l);
            }
            #pragma unroll
            for (int r = 0; r < 8; ++r) {
                const int y = y0 + r;
                if (y < 127) {
                    uN4 = __ldg(up4 + ((y + 1) << 5) + l);
                    vN4 = __ldg(vp4 + ((y + 1) << 5) + l);
                }
                float uL = __shfl_sync(0xffffffffu, uC4.w, lm);
                float uR = __shfl_sync(0xffffffffu, uC4.x, lp);
                float vL = __shfl_sync(0xffffffffu, vC4.w, lm);
                float vR = __shfl_sync(0xffffffffu, vC4.x, lp);
                if (y >= 1 && y <= 126) {
                    float ue[4] = {uC4.y, uC4.z, uC4.w, uR};
                    float uw[4] = {uL, uC4.x, uC4.y, uC4.z};
                    float ve[4] = {vC4.y, vC4.z, vC4.w, vR};
                    float vw[4] = {vL, vC4.x, vC4.y, vC4.z};
                    float un_[4] = {uN4.x, uN4.y, uN4.z, uN4.w};
                    float us_[4] = {uP4.x, uP4.y, uP4.z, uP4.w};
                    float vn_[4] = {vN4.x, vN4.y, vN4.z, vN4.w};
                    float vs_[4] = {vP4.x, vP4.y, vP4.z, vP4.w};
                    float m[4];
                    #pragma unroll
                    for (int j = 0; j < 4; ++j) {
                        float dudx = (ue[j] - uw[j]) * INV2DX;
                        float dvdy = (vn_[j] - vs_[j]) * INV2DY;
                        float dudy = (un_[j] - us_[j]) * INV2DY;
                        float dvdx = (ve[j] - vw[j]) * INV2DX;
                        float bt = (dudx + dvdy) * INVDT - dudx * dudx
                                   - 2.0f * dudy * dvdx - dvdy * dvdy;
                        m[j] = -CF * bt;
                    }
                    mA[r] = pk2(m[0], m[1]);
                    mB[r] = pk2(m[2], m[3]);
                } else {
                    mA[r] = 0ull; mB[r] = 0ull;
                }
                uP4 = uC4; uC4 = uN4; vP4 = vC4; vC4 = vN4;
            }
        }

        // ---- 20 Jacobi sweeps, p packed in registers, halo rows via smem ----
        #pragma unroll 1
        for (int s = 0; s < 20; ++s) {
            float* hb = halo + (s & 1) * 4096;
            *(ulonglong2*)(hb + (wid << 7) + x0) = make_ulonglong2(pA[0], pB[0]);
            *(ulonglong2*)(hb + ((16 + wid) << 7) + x0) = make_ulonglong2(pA[7], pB[7]);
            __syncthreads();
            ulonglong2 hS = make_ulonglong2(0, 0), hN = make_ulonglong2(0, 0);
            if (wid > 0)  hS = *(const ulonglong2*)(hb + ((15 + wid) << 7) + x0);
            if (wid < 15) hN = *(const ulonglong2*)(hb + ((wid + 1) << 7) + x0);

            ull tSA, tSB, nA, nB;
            if (wid == 0) {   // y=0 mirror row: no compute
                tSA = pA[0]; tSB = pB[0];
            } else {
                jrow2(pA[0], pB[0], hS.x, hS.y, pA[1], pB[1],
                      mA[0], mB[0], AEW2, ANS2, lm, lp, nA, nB);
                tSA = pA[0]; tSB = pB[0]; pA[0] = nA; pB[0] = nB;
            }
            #pragma unroll
            for (int r = 1; r < 7; ++r) {
                jrow2(pA[r], pB[r], tSA, tSB, pA[r + 1], pB[r + 1],
                      mA[r], mB[r], AEW2, ANS2, lm, lp, nA, nB);
                ull oA = pA[r], oB = pB[r];
                pA[r] = nA; pB[r] = nB;
                tSA = oA; tSB = oB;
            }
            if (wid < 15) {
                jrow2(pA[7], pB[7], tSA, tSB, hN.x, hN.y,
                      mA[7], mB[7], AEW2, ANS2, lm, lp, nA, nB);
                pA[7] = nA; pB[7] = nB;
            }
            if (wid == 0)  { pA[0] = pA[1]; pB[0] = pB[1]; }   // p[0]=p[1]
            if (wid == 15) { pA[7] = pA[6]; pB[7] = pB[6]; }   // p[127]=p[126]
        }

        // ---- velocity step (dead on last iteration: output is p only) ----
        if (it < 2) {
            // exchange final p halos (buf0)
            *(ulonglong2*)(halo + (wid << 7) + x0) = make_ulonglong2(pA[0], pB[0]);
            *(ulonglong2*)(halo + ((16 + wid) << 7) + x0) = make_ulonglong2(pA[7], pB[7]);
            __syncthreads();
            float pAh[4] = {0,0,0,0}, pBh[4] = {0,0,0,0};
            if (wid > 0) {
                ulonglong2 q = *(const ulonglong2*)(halo + ((15 + wid) << 7) + x0);
                upk2(q.x, pAh[0], pAh[1]); upk2(q.y, pAh[2], pAh[3]);
            }
            if (wid < 15) {
                ulonglong2 q = *(const ulonglong2*)(halo + ((wid + 1) << 7) + x0);
                upk2(q.x, pBh[0], pBh[1]); upk2(q.y, pBh[2], pBh[3]);
            }

            float4 uP4 = make_float4(0,0,0,0), vP4 = uP4;
            float4 uN4 = uP4, vN4 = uP4;
            float4 uC4 = __ldg(up4 + (y0 << 5) + l);
            float4 vC4 = __ldg(vp4 + (y0 << 5) + l);
            if (wid > 0) {
                uP4 = __ldg(up4 + ((y0 - 1) << 5) + l);
                vP4 = __ldg(vp4 + ((y0 - 1) << 5) + l);
            }
            float psP[4], psC[4], psN[4];
            upk2(pA[0], psC[0], psC[1]); upk2(pB[0], psC[2], psC[3]);

            #pragma unroll
            for (int r = 0; r < 8; ++r) {
                const int y = y0 + r;
                if (y < 127) {
                    uN4 = __ldg(up4 + ((y + 1) << 5) + l);
                    vN4 = __ldg(vp4 + ((y + 1) << 5) + l);
                }
                if (r < 7) {
                    upk2(pA[r + 1], psN[0], psN[1]);
                    upk2(pB[r + 1], psN[2], psN[3]);
                } else {
                    #pragma unroll
                    for (int j = 0; j < 4; ++j) psN[j] = pBh[j];
                }
                float uL = __shfl_sync(0xffffffffu, uC4.w, lm);
                float uR = __shfl_sync(0xffffffffu, uC4.x, lp);
                float vL = __shfl_sync(0xffffffffu, vC4.w, lm);
                float vR = __shfl_sync(0xffffffffu, vC4.x, lp);
                float wLp = __shfl_sync(0xffffffffu, psC[3], lm);
                float eRp = __shfl_sync(0xffffffffu, psC[0], lp);

                float* uoy = uo + (y << 7);
                float* voy = vo + (y << 7);
                if (y == 0 || y == 127) {
                    *(float4*)(uoy + x0) = make_float4(0.f, 0.f, 0.f, 0.f);
                    *(float4*)(voy + x0) = make_float4(0.f, 0.f, 0.f, 0.f);
                } else {
                    float ucv[4] = {uC4.x, uC4.y, uC4.z, uC4.w};
                    float ue[4]  = {uC4.y, uC4.z, uC4.w, uR};
                    float uw[4]  = {uL, uC4.x, uC4.y, uC4.z};
                    float un_[4] = {uN4.x, uN4.y, uN4.z, uN4.w};
                    float us_[4] = {uP4.x, uP4.y, uP4.z, uP4.w};
                    float vcv[4] = {vC4.x, vC4.y, vC4.z, vC4.w};
                    float ve[4]  = {vC4.y, vC4.z, vC4.w, vR};
                    float vw[4]  = {vL, vC4.x, vC4.y, vC4.z};
                    float vn_[4] = {vN4.x, vN4.y, vN4.z, vN4.w};
                    float vs_[4] = {vP4.x, vP4.y, vP4.z, vP4.w};
                    float pe[4]  = {psC[1], psC[2], psC[3], eRp};
                    float pw[4]  = {wLp, psC[0], psC[1], psC[2]};

                    float unew[4], vnew[4];
                    #pragma unroll
                    for (int j = 0; j < 4; ++j) {
                        float ps = (r == 0) ? pAh[j] : psP[j];
                        float pn = psN[j];
                        float uc = ucv[j], vc = vcv[j];
                        float lapu = DTDX2 * (ue[j] - 2.f * uc + uw[j])
                                   + DTDY2 * (un_[j] - 2.f * uc + us_[j]);
                        float lapv = DTDX2 * (ve[j] - 2.f * vc + vw[j])
                                   + DTDY2 * (vn_[j] - 2.f * vc + vs_[j]);
                        unew[j] = uc - uc * DTDX * (uc - uw[j]) - vc * DTDY * (uc - us_[j])
                                  - PXC * (pe[j] - pw[j]) + NUF * lapu + FDT;
                        vnew[j] = vc - uc * DTDX * (vc - vw[j]) - vc * DTDY * (vc - vs_[j])
                                  - PYC * (pn - ps) + NUF * lapv;
                    }
                    *(float4*)(uoy + x0) = make_float4(unew[0], unew[1], unew[2], unew[3]);
                    *(float4*)(voy + x0) = make_float4(vnew[0], vnew[1], vnew[2], vnew[3]);
                }
                uP4 = uC4; uC4 = uN4; vP4 = vC4; vC4 = vN4;
                #pragma unroll
                for (int j = 0; j < 4; ++j) { psP[j] = psC[j]; psC[j] = psN[j]; }
            }
            __syncthreads();   // u/v + halo visibility before next iteration
        }
    }

    // ---- output: p[:, -1, :, :] = row 127 (mirror of 126, warp 15 regs) ----
    if (wid == 15) {
        float o0, o1, o2, o3;
        upk2(pA[7], o0, o1); upk2(pB[7], o2, o3);
        float* ob = out + (size_t)b * 4096 + (size_t)x0 * 32 + d;
        ob[0]  = o0;
        ob[32] = o1;
        ob[64] = o2;
        ob[96] = o3;
    }
}

// ---------------------------------------------------------------------------
extern "C" void kernel_launch(void* const* d_in, const int* in_sizes, int n_in,
                              void* d_out, int out_size) {
    const float* x  = (const float*)d_in[0];   // (8,126,126,64)
    const float* u0 = (const float*)d_in[1];   // (8,128,128,32)
    const float* v0 = (const float*)d_in[2];   // (8,128,128,32)
    const float* w  = (const float*)d_in[3];   // (32,64)
    const float* bl = (const float*)d_in[4];   // (32,)
    float* out = (float*)d_out;                // (8,128,32)

    (void)in_sizes; (void)n_in; (void)out_size;

    prep_kernel<<<4608, 256>>>(u0, v0, x, w, bl);
    sim_kernel<<<256, 512>>>(out);
}

// round 12
// speedup vs baseline: 3.2477x; 1.0405x over previous
#include <cuda_runtime.h>
#include <cstdint>

// 256 independent sims of 128x128. Ping-pong u/v scratch + precomputed p-init,
// all in (b,d,y,x) layout.
static __device__ float g_u[2][(size_t)256 * 16384];
static __device__ float g_v[2][(size_t)256 * 16384];
static __device__ float g_p[(size_t)256 * 16384];

// ---- constants (double, cast to float to mirror numpy f32 ops) ----
constexpr double DXd  = 2.0 / 9.0;      // 2/(B+1), B=8
constexpr double DYd  = 2.0 / 127.0;    // 2/(H+1), H=126
constexpr double DX2d = DXd * DXd;
constexpr double DY2d = DYd * DYd;
constexpr double DENd = 2.0 * (DX2d + DY2d);

constexpr float AEW    = (float)(DY2d / DENd);   // coeff for (E+W)
constexpr float ANS    = (float)(DX2d / DENd);   // coeff for (N+S)
constexpr float CF     = (float)(DX2d * DY2d / DENd);
constexpr float INV2DX = (float)(1.0 / (2.0 * DXd));
constexpr float INV2DY = (float)(1.0 / (2.0 * DYd));
constexpr float INVDT  = 10.0f;
constexpr float DTDX   = (float)(0.1 / DXd);
constexpr float DTDY   = (float)(0.1 / DYd);
constexpr float DTDX2  = (float)(0.1 / DX2d);
constexpr float DTDY2  = (float)(0.1 / DY2d);
constexpr float NUF    = 0.1f;
constexpr float PXC    = (float)(0.1 / (2.0 * DXd));   // DT/(2*RHO*DX)
constexpr float PYC    = (float)(0.1 / (2.0 * DYd));   // DT/(2*RHO*DY)
constexpr float FDT    = 0.1f;                         // FRC*DT

typedef unsigned long long ull;

// ---- packed f32x2 helpers ----
__device__ __forceinline__ ull pk2(float lo, float hi) {
    ull r; asm("mov.b64 %0, {%1,%2};" : "=l"(r) : "f"(lo), "f"(hi)); return r;
}
__device__ __forceinline__ void upk2(ull v, float& lo, float& hi) {
    asm("mov.b64 {%0,%1}, %2;" : "=f"(lo), "=f"(hi) : "l"(v));
}
__device__ __forceinline__ ull add2_(ull a, ull b) {
    ull d; asm("add.rn.f32x2 %0, %1, %2;" : "=l"(d) : "l"(a), "l"(b)); return d;
}
__device__ __forceinline__ ull fma2_(ull a, ull b, ull c) {
    ull d; asm("fma.rn.f32x2 %0, %1, %2, %3;" : "=l"(d) : "l"(a), "l"(b), "l"(c)); return d;
}

// ---------------------------------------------------------------------------
// K1 (fused prep): blocks [0,1024) compute p-init einsum (long compute —
// scheduled FIRST so they overlap the transpose's DRAM traffic);
// blocks [1024,5120) transpose u0,v0 (b,yx,d)->(b,d,yx).
// 256 threads per block.
// ---------------------------------------------------------------------------
__global__ void __launch_bounds__(256) prep_kernel(
    const float* __restrict__ u0, const float* __restrict__ v0,
    const float* __restrict__ x,  const float* __restrict__ w,
    const float* __restrict__ b_lin)
{
    __shared__ float s0[32][33];
    __shared__ float s1[32][33];
    const int bid = blockIdx.x;
    const int t   = threadIdx.x;

    if (bid < 1024) {
        // ---- einsum role: block = (b, y); thread = (dg, tx) ----
        float* ws  = &s0[0][0];           // 2048 floats fit in s0+s1 (2112)
        float* bls = &s1[31][0];          // 32 floats, disjoint tail
        for (int i = t; i < 2048; i += 256) ws[i] = __ldg(w + i);
        if (t < 32) bls[t] = __ldg(b_lin + t);
        __syncthreads();

        const int b  = bid >> 7;
        const int y  = bid & 127;
        const int dg = t >> 7;            // 0/1 -> d in [16dg, 16dg+16)
        const int tx = t & 127;

        float* gp = g_p + ((size_t)b << 19) + ((size_t)(dg * 16) << 14)
                        + y * 128 + tx;   // +16384 per d
        if (y == 0 || y == 127 || tx == 0 || tx == 127) {
            #pragma unroll 1
            for (int d = 0; d < 16; ++d) gp[(size_t)d << 14] = bls[dg * 16 + d];
            return;
        }
        float xv[64];
        const float4* xr = (const float4*)(x +
            (((size_t)b * 126 + (y - 1)) * 126 + (tx - 1)) * 64);
        #pragma unroll
        for (int i = 0; i < 16; ++i) {
            float4 q = __ldg(xr + i);
            xv[4*i] = q.x; xv[4*i+1] = q.y; xv[4*i+2] = q.z; xv[4*i+3] = q.w;
        }
        #pragma unroll 1
        for (int d = 0; d < 16; ++d) {
            const float4* wv = (const float4*)(ws + ((dg * 16 + d) << 6));
            float a0 = 0.f, a1 = 0.f, a2 = 0.f, a3 = 0.f;
            #pragma unroll
            for (int i = 0; i < 16; ++i) {
                float4 q = wv[i];
                a0 = fmaf(xv[4*i],   q.x, a0);
                a1 = fmaf(xv[4*i+1], q.y, a1);
                a2 = fmaf(xv[4*i+2], q.z, a2);
                a3 = fmaf(xv[4*i+3], q.w, a3);
            }
            gp[(size_t)d << 14] = (a0 + a1) + (a2 + a3) + bls[dg * 16 + d];
        }
    } else {
        // ---- transpose role ----
        const int bid2 = bid - 1024;
        const int b   = bid2 >> 9;
        const int yx0 = (bid2 & 511) * 32;
        const int tx  = t & 31;
        const int ty  = t >> 5;          // 0..7
        const float* ub = u0 + (size_t)b * 16384 * 32;
        const float* vb = v0 + (size_t)b * 16384 * 32;
        #pragma unroll
        for (int r = ty; r < 32; r += 8) {
            s0[r][tx] = ub[(size_t)(yx0 + r) * 32 + tx];
            s1[r][tx] = vb[(size_t)(yx0 + r) * 32 + tx];
        }
        __syncthreads();
        #pragma unroll
        for (int r = ty; r < 32; r += 8) {   // r = d, tx = local yx
            size_t o = ((size_t)b * 32 + r) * 16384 + yx0 + tx;
            g_u[0][o] = s0[tx][r];
            g_v[0][o] = s1[tx][r];
        }
    }
}

// Packed Jacobi row update. E/W sums as scalar FADDs (fresh defs -> ptxas can
// allocate them as aligned pairs, no forced repack movs); rest packed f32x2.
__device__ __forceinline__ void jrow2(ull a, ull bq, ull SA, ull SB,
                                      ull NA, ull NB, ull mA, ull mB,
                                      ull AEW2, ull ANS2, int lm, int lp,
                                      ull& oA, ull& oB)
{
    float c0, c1, c2, c3;
    upk2(a, c0, c1); upk2(bq, c2, c3);           // free: pair-half aliases
    float wL = __shfl_sync(0xffffffffu, c3, lm);
    float eR = __shfl_sync(0xffffffffu, c0, lp);
    float ew0 = wL + c1;
    float ew1 = c0 + c2;
    float ew2 = c1 + c3;
    float ew3 = c2 + eR;
    ull EWA = pk2(ew0, ew1);
    ull EWB = pk2(ew2, ew3);
    oA = fma2_(EWA, AEW2, fma2_(add2_(SA, NA), ANS2, mA));
    oB = fma2_(EWB, AEW2, fma2_(add2_(SB, NB), ANS2, mB));
}

// ---------------------------------------------------------------------------
// K2: persistent sim kernel. One CTA per (b,d). p register-resident (packed):
// warp w owns rows 8w..8w+7; lane l owns x = 4l..4l+3. Halo rows via smem.
// ---------------------------------------------------------------------------
__global__ void __launch_bounds__(512, 1) sim_kernel(float* __restrict__ out)
{
    __shared__ float halo[2 * 2 * 16 * 128];   // 32 KB, double-buffered
    const int t   = threadIdx.x;
    const int wid = t >> 5;
    const int l   = t & 31;
    const int bi  = blockIdx.x;
    const int b   = bi >> 5, d = bi & 31;
    const int y0  = wid << 3;
    const int x0  = l << 2;
    const size_t so = (size_t)bi << 14;

    const int lm = (l + 31) & 31;
    const int lp = (l + 1)  & 31;

    const ull AEW2 = pk2(AEW, AEW);
    const ull ANS2 = pk2(ANS, ANS);

    // ---- load p-init into packed registers ----
    ull pA[8], pB[8];
    {
        const float4* gp = (const float4*)(g_p + so);
        #pragma unroll
        for (int r = 0; r < 8; ++r) {
            float4 q = __ldg(gp + ((y0 + r) << 5) + l);
            pA[r] = pk2(q.x, q.y);
            pB[r] = pk2(q.z, q.w);
        }
    }

    ull mA[8], mB[8];

    #pragma unroll 1
    for (int it = 0; it < 3; ++it) {
        const float4* __restrict__ up4 = (const float4*)(g_u[it & 1] + so);
        const float4* __restrict__ vp4 = (const float4*)(g_v[it & 1] + so);
        float* __restrict__ uo = g_u[(it & 1) ^ 1] + so;
        float* __restrict__ vo = g_v[(it & 1) ^ 1] + so;

        // ---- build_b -> mcb (packed, registers). Rolling 3-row window. ----
        {
            float4 uP4 = make_float4(0,0,0,0), vP4 = uP4;
            float4 uN4 = uP4, vN4 = uP4;
            float4 uC4 = __ldg(up4 + (y0 << 5) + l);
            float4 vC4 = __ldg(vp4 + (y0 << 5) + l);
            if (wid > 0) {
                uP4 = __ldg(up4 + ((y0 - 1) << 5) + l);
                vP4 = __ldg(vp4 + ((y0 - 1) << 5) + l);
            }
            #pragma unroll
            for (int r = 0; r < 8; ++r) {
                const int y = y0 + r;
                if (y < 127) {
                    uN4 = __ldg(up4 + ((y + 1) << 5) + l);
                    vN4 = __ldg(vp4 + ((y + 1) << 5) + l);
                }
                float uL = __shfl_sync(0xffffffffu, uC4.w, lm);
                float uR = __shfl_sync(0xffffffffu, uC4.x, lp);
                float vL = __shfl_sync(0xffffffffu, vC4.w, lm);
                float vR = __shfl_sync(0xffffffffu, vC4.x, lp);
                if (y >= 1 && y <= 126) {
                    float ue[4] = {uC4.y, uC4.z, uC4.w, uR};
                    float uw[4] = {uL, uC4.x, uC4.y, uC4.z};
                    float ve[4] = {vC4.y, vC4.z, vC4.w, vR};
                    float vw[4] = {vL, vC4.x, vC4.y, vC4.z};
                    float un_[4] = {uN4.x, uN4.y, uN4.z, uN4.w};
                    float us_[4] = {uP4.x, uP4.y, uP4.z, uP4.w};
                    float vn_[4] = {vN4.x, vN4.y, vN4.z, vN4.w};
                    float vs_[4] = {vP4.x, vP4.y, vP4.z, vP4.w};
                    float m[4];
                    #pragma unroll
                    for (int j = 0; j < 4; ++j) {
                        float dudx = (ue[j] - uw[j]) * INV2DX;
                        float dvdy = (vn_[j] - vs_[j]) * INV2DY;
                        float dudy = (un_[j] - us_[j]) * INV2DY;
                        float dvdx = (ve[j] - vw[j]) * INV2DX;
                        float bt = (dudx + dvdy) * INVDT - dudx * dudx
                                   - 2.0f * dudy * dvdx - dvdy * dvdy;
                        m[j] = -CF * bt;
                    }
                    mA[r] = pk2(m[0], m[1]);
                    mB[r] = pk2(m[2], m[3]);
                } else {
                    mA[r] = 0ull; mB[r] = 0ull;
                }
                uP4 = uC4; uC4 = uN4; vP4 = vC4; vC4 = vN4;
            }
        }

        // ---- 20 Jacobi sweeps, p packed in registers, halo rows via smem ----
        #pragma unroll 1
        for (int s = 0; s < 20; ++s) {
            float* hb = halo + (s & 1) * 4096;
            *(ulonglong2*)(hb + (wid << 7) + x0) = make_ulonglong2(pA[0], pB[0]);
            *(ulonglong2*)(hb + ((16 + wid) << 7) + x0) = make_ulonglong2(pA[7], pB[7]);
            __syncthreads();
            ulonglong2 hS = make_ulonglong2(0, 0), hN = make_ulonglong2(0, 0);
            if (wid > 0)  hS = *(const ulonglong2*)(hb + ((15 + wid) << 7) + x0);
            if (wid < 15) hN = *(const ulonglong2*)(hb + ((wid + 1) << 7) + x0);

            ull tSA, tSB, nA, nB;
            if (wid == 0) {   // y=0 mirror row: no compute
                tSA = pA[0]; tSB = pB[0];
            } else {
                jrow2(pA[0], pB[0], hS.x, hS.y, pA[1], pB[1],
                      mA[0], mB[0], AEW2, ANS2, lm, lp, nA, nB);
                tSA = pA[0]; tSB = pB[0]; pA[0] = nA; pB[0] = nB;
            }
            #pragma unroll
            for (int r = 1; r < 7; ++r) {
                jrow2(pA[r], pB[r], tSA, tSB, pA[r + 1], pB[r + 1],
                      mA[r], mB[r], AEW2, ANS2, lm, lp, nA, nB);
                ull oA = pA[r], oB = pB[r];
                pA[r] = nA; pB[r] = nB;
                tSA = oA; tSB = oB;
            }
            if (wid < 15) {
                jrow2(pA[7], pB[7], tSA, tSB, hN.x, hN.y,
                      mA[7], mB[7], AEW2, ANS2, lm, lp, nA, nB);
                pA[7] = nA; pB[7] = nB;
            }
            if (wid == 0)  { pA[0] = pA[1]; pB[0] = pB[1]; }   // p[0]=p[1]
            if (wid == 15) { pA[7] = pA[6]; pB[7] = pB[6]; }   // p[127]=p[126]
        }

        // ---- velocity step (dead on last iteration: output is p only) ----
        if (it < 2) {
            // exchange final p halos (buf0)
            *(ulonglong2*)(halo + (wid << 7) + x0) = make_ulonglong2(pA[0], pB[0]);
            *(ulonglong2*)(halo + ((16 + wid) << 7) + x0) = make_ulonglong2(pA[7], pB[7]);
            __syncthreads();
            float pAh[4] = {0,0,0,0}, pBh[4] = {0,0,0,0};
            if (wid > 0) {
                ulonglong2 q = *(const ulonglong2*)(halo + ((15 + wid) << 7) + x0);
                upk2(q.x, pAh[0], pAh[1]); upk2(q.y, pAh[2], pAh[3]);
            }
            if (wid < 15) {
                ulonglong2 q = *(const ulonglong2*)(halo + ((wid + 1) << 7) + x0);
                upk2(q.x, pBh[0], pBh[1]); upk2(q.y, pBh[2], pBh[3]);
            }

            float4 uP4 = make_float4(0,0,0,0), vP4 = uP4;
            float4 uN4 = uP4, vN4 = uP4;
            float4 uC4 = __ldg(up4 + (y0 << 5) + l);
            float4 vC4 = __ldg(vp4 + (y0 << 5) + l);
            if (wid > 0) {
                uP4 = __ldg(up4 + ((y0 - 1) << 5) + l);
                vP4 = __ldg(vp4 + ((y0 - 1) << 5) + l);
            }
            float psP[4], psC[4], psN[4];
            upk2(pA[0], psC[0], psC[1]); upk2(pB[0], psC[2], psC[3]);

            #pragma unroll
            for (int r = 0; r < 8; ++r) {
                const int y = y0 + r;
                if (y < 127) {
                    uN4 = __ldg(up4 + ((y + 1) << 5) + l);
                    vN4 = __ldg(vp4 + ((y + 1) << 5) + l);
                }
                if (r < 7) {
                    upk2(pA[r + 1], psN[0], psN[1]);
                    upk2(pB[r + 1], psN[2], psN[3]);
                } else {
                    #pragma unroll
                    for (int j = 0; j < 4; ++j) psN[j] = pBh[j];
                }
                float uL = __shfl_sync(0xffffffffu, uC4.w, lm);
                float uR = __shfl_sync(0xffffffffu, uC4.x, lp);
                float vL = __shfl_sync(0xffffffffu, vC4.w, lm);
                float vR = __shfl_sync(0xffffffffu, vC4.x, lp);
                float wLp = __shfl_sync(0xffffffffu, psC[3], lm);
                float eRp = __shfl_sync(0xffffffffu, psC[0], lp);

                float* uoy = uo + (y << 7);
                float* voy = vo + (y << 7);
                if (y == 0 || y == 127) {
                    *(float4*)(uoy + x0) = make_float4(0.f, 0.f, 0.f, 0.f);
                    *(float4*)(voy + x0) = make_float4(0.f, 0.f, 0.f, 0.f);
                } else {
                    float ucv[4] = {uC4.x, uC4.y, uC4.z, uC4.w};
                    float ue[4]  = {uC4.y, uC4.z, uC4.w, uR};
                    float uw[4]  = {uL, uC4.x, uC4.y, uC4.z};
                    float un_[4] = {uN4.x, uN4.y, uN4.z, uN4.w};
                    float us_[4] = {uP4.x, uP4.y, uP4.z, uP4.w};
                    float vcv[4] = {vC4.x, vC4.y, vC4.z, vC4.w};
                    float ve[4]  = {vC4.y, vC4.z, vC4.w, vR};
                    float vw[4]  = {vL, vC4.x, vC4.y, vC4.z};
                    float vn_[4] = {vN4.x, vN4.y, vN4.z, vN4.w};
                    float vs_[4] = {vP4.x, vP4.y, vP4.z, vP4.w};
                    float pe[4]  = {psC[1], psC[2], psC[3], eRp};
                    float pw[4]  = {wLp, psC[0], psC[1], psC[2]};

                    float unew[4], vnew[4];
                    #pragma unroll
                    for (int j = 0; j < 4; ++j) {
                        float ps = (r == 0) ? pAh[j] : psP[j];
                        float pn = psN[j];
                        float uc = ucv[j], vc = vcv[j];
                        float lapu = DTDX2 * (ue[j] - 2.f * uc + uw[j])
                                   + DTDY2 * (un_[j] - 2.f * uc + us_[j]);
                        float lapv = DTDX2 * (ve[j] - 2.f * vc + vw[j])
                                   + DTDY2 * (vn_[j] - 2.f * vc + vs_[j]);
                        unew[j] = uc - uc * DTDX * (uc - uw[j]) - vc * DTDY * (uc - us_[j])
                                  - PXC * (pe[j] - pw[j]) + NUF * lapu + FDT;
                        vnew[j] = vc - uc * DTDX * (vc - vw[j]) - vc * DTDY * (vc - vs_[j])
                                  - PYC * (pn - ps) + NUF * lapv;
                    }
                    *(float4*)(uoy + x0) = make_float4(unew[0], unew[1], unew[2], unew[3]);
                    *(float4*)(voy + x0) = make_float4(vnew[0], vnew[1], vnew[2], vnew[3]);
                }
                uP4 = uC4; uC4 = uN4; vP4 = vC4; vC4 = vN4;
                #pragma unroll
                for (int j = 0; j < 4; ++j) { psP[j] = psC[j]; psC[j] = psN[j]; }
            }
            __syncthreads();   // u/v + halo visibility before next iteration
        }
    }

    // ---- output: p[:, -1, :, :] = row 127 (mirror of 126, warp 15 regs) ----
    if (wid == 15) {
        float o0, o1, o2, o3;
        upk2(pA[7], o0, o1); upk2(pB[7], o2, o3);
        float* ob = out + (size_t)b * 4096 + (size_t)x0 * 32 + d;
        ob[0]  = o0;
        ob[32] = o1;
        ob[64] = o2;
        ob[96] = o3;
    }
}

// ---------------------------------------------------------------------------
extern "C" void kernel_launch(void* const* d_in, const int* in_sizes, int n_in,
                              void* d_out, int out_size) {
    const float* x  = (const float*)d_in[0];   // (8,126,126,64)
    const float* u0 = (const float*)d_in[1];   // (8,128,128,32)
    const float* v0 = (const float*)d_in[2];   // (8,128,128,32)
    const float* w  = (const float*)d_in[3];   // (32,64)
    const float* bl = (const float*)d_in[4];   // (32,)
    float* out = (float*)d_out;                // (8,128,32)

    (void)in_sizes; (void)n_in; (void)out_size;

    prep_kernel<<<5120, 256>>>(u0, v0, x, w, bl);
    sim_kernel<<<256, 512>>>(out);
}